// round 9
// baseline (speedup 1.0000x reference)
#include <cuda_runtime.h>
#include <mma.h>
#include <cstdint>

using namespace nvcuda;

#define NNODES 500000
#define CDIM   128
#define HDIM   256
#define ADIM   10
#define BROWS  (NNODES / ADIM)
#define EMAX   600000

// ---------------- scratch (device globals) -----------------------------------
__device__ __align__(16) float g_xn [(size_t)NNODES * CDIM];
__device__ __align__(16) float g_y  [(size_t)BROWS * CDIM];
__device__ __align__(16) float g_h1 [(size_t)BROWS * HDIM];
__device__ int   g_deg[NNODES];
__device__ int   g_rowptr[NNODES];
__device__ int   g_cursor[NNODES];
__device__ int   g_col[EMAX];
__device__ int   g_bsum[1024];

// ---------------- small kernels ----------------------------------------------
__global__ void zero_deg_kernel(int n) {
    int i = blockIdx.x * blockDim.x + threadIdx.x;
    if (i < n) g_deg[i] = 0;
}
__global__ void count_deg_kernel(const int* __restrict__ dst, int E, int N) {
    int e = blockIdx.x * blockDim.x + threadIdx.x;
    if (e < E) {
        int d = dst[e];
        if (d >= 0 && d < N) atomicAdd(&g_deg[d], 1);
    }
}
__global__ void init_out_kernel(float* __restrict__ out, const float* __restrict__ b3, int B) {
    int i = blockIdx.x * blockDim.x + threadIdx.x;
    if (i < B) out[i] = b3[0];
}

// ---------------- prefix scan (3 kernels) -------------------------------------
__global__ void __launch_bounds__(256) scan1_kernel(int n) {
    __shared__ int warp_sums[8];
    const int tid = threadIdx.x, lane = tid & 31, wid = tid >> 5;
    const int gbase = blockIdx.x * 1024 + tid * 4;
    int v[4]; int t = 0;
#pragma unroll
    for (int j = 0; j < 4; j++) { v[j] = (gbase + j < n) ? g_deg[gbase + j] : 0; t += v[j]; }
    int inc = t;
#pragma unroll
    for (int o = 1; o < 32; o <<= 1) { int x = __shfl_up_sync(~0u, inc, o); if (lane >= o) inc += x; }
    if (lane == 31) warp_sums[wid] = inc;
    __syncthreads();
    if (wid == 0) {
        int ws = (lane < 8) ? warp_sums[lane] : 0;
#pragma unroll
        for (int o = 1; o < 8; o <<= 1) { int x = __shfl_up_sync(~0u, ws, o); if (lane >= o) ws += x; }
        if (lane < 8) warp_sums[lane] = ws;
    }
    __syncthreads();
    int block_excl = (wid > 0) ? warp_sums[wid - 1] : 0;
    int run = block_excl + inc - t;
#pragma unroll
    for (int j = 0; j < 4; j++) { if (gbase + j < n) g_rowptr[gbase + j] = run; run += v[j]; }
    if (tid == 0) g_bsum[blockIdx.x] = warp_sums[7];
}
__global__ void __launch_bounds__(512) scan2_kernel(int nb) {
    __shared__ int sh[512];
    const int tid = threadIdx.x;
    int v = (tid < nb) ? g_bsum[tid] : 0;
    sh[tid] = v;
    __syncthreads();
    for (int o = 1; o < 512; o <<= 1) {
        int x = (tid >= o) ? sh[tid - o] : 0;
        __syncthreads();
        sh[tid] += x;
        __syncthreads();
    }
    if (tid < nb) g_bsum[tid] = sh[tid] - v;
}
__global__ void __launch_bounds__(256) scan3_kernel(int n) {
    const int gbase = blockIdx.x * 1024 + threadIdx.x * 4;
    const int off = g_bsum[blockIdx.x];
#pragma unroll
    for (int j = 0; j < 4; j++) {
        int i = gbase + j;
        if (i < n) { int r = g_rowptr[i] + off; g_rowptr[i] = r; g_cursor[i] = r; }
    }
}
__global__ void fill_kernel(const int* __restrict__ src, const int* __restrict__ dst,
                            int E, int N) {
    int e = blockIdx.x * blockDim.x + threadIdx.x;
    if (e >= E) return;
    int d = dst[e], s = src[e];
    if (d < 0 || d >= N || s < 0 || s >= N) return;
    int pos = atomicAdd(&g_cursor[d], 1);
    if (pos >= 0 && pos < EMAX) g_col[pos] = s;
}

// ---------------- wmma tf32 GEMM core v3 ---------------------------------------
// Block 256 thr (8 warps as 4M x 2N). Block tile 128x128, warp tile 32x64.
// K-chunks of 32. tf32 cvt at SMEM store; register prefetch of next chunk.
// Per k-step: 6 fragment loads for 8 MMAs (3 LDS/MMA vs 4 before).
#define LDA 36
#define LDW 132
#define OFF_WS (128 * LDA * 4)               // 18432 B
#define SMEM_GEMM (OFF_WS + 32 * LDW * 4)    // 35328 B; stage (64x128x4=32768) overlays

template <int K, int NW>
__device__ __forceinline__ void wmma_core(
    const float* __restrict__ A, const float* __restrict__ W,
    char* sh, int m0, int n0, int M,
    wmma::fragment<wmma::accumulator, 16, 16, 8, float> acc[2][4])
{
    float* As = (float*)sh;
    float* Ws = (float*)(sh + OFF_WS);
    const int tid = threadIdx.x;
    const int wid = tid >> 5;
    const int wm  = (wid & 3) * 32;
    const int wn  = (wid >> 2) * 64;

#pragma unroll
    for (int i = 0; i < 2; i++)
#pragma unroll
        for (int j = 0; j < 4; j++) wmma::fill_fragment(acc[i][j], 0.0f);

    float4 ra[4], rw[4];

    // prologue: chunk 0 into registers (A: 128x32 = 1024 f4; W: 32x128 = 1024 f4)
#pragma unroll
    for (int i = 0; i < 4; i++) {
        int f = tid + i * 256;
        int m = f >> 3, k4 = f & 7;
        ra[i] = make_float4(0.f, 0.f, 0.f, 0.f);
        if (m0 + m < M)
            ra[i] = *(const float4*)&A[(size_t)(m0 + m) * K + k4 * 4];
    }
#pragma unroll
    for (int i = 0; i < 4; i++) {
        int f = tid + i * 256;
        int k = f >> 5, n4 = f & 31;
        rw[i] = *(const float4*)&W[(size_t)k * NW + n0 + n4 * 4];
    }

    const int nchunks = K / 32;
    for (int c = 0; c < nchunks; c++) {
#pragma unroll
        for (int i = 0; i < 4; i++) {
            int f = tid + i * 256;
            int m = f >> 3, k4 = f & 7;
            float4 v = ra[i];
            v.x = wmma::__float_to_tf32(v.x); v.y = wmma::__float_to_tf32(v.y);
            v.z = wmma::__float_to_tf32(v.z); v.w = wmma::__float_to_tf32(v.w);
            *(float4*)&As[m * LDA + k4 * 4] = v;
        }
#pragma unroll
        for (int i = 0; i < 4; i++) {
            int f = tid + i * 256;
            int k = f >> 5, n4 = f & 31;
            float4 v = rw[i];
            v.x = wmma::__float_to_tf32(v.x); v.y = wmma::__float_to_tf32(v.y);
            v.z = wmma::__float_to_tf32(v.z); v.w = wmma::__float_to_tf32(v.w);
            *(float4*)&Ws[k * LDW + n4 * 4] = v;
        }
        __syncthreads();

        if (c + 1 < nchunks) {
            int kb = (c + 1) * 32;
#pragma unroll
            for (int i = 0; i < 4; i++) {
                int f = tid + i * 256;
                int m = f >> 3, k4 = f & 7;
                ra[i] = make_float4(0.f, 0.f, 0.f, 0.f);
                if (m0 + m < M)
                    ra[i] = *(const float4*)&A[(size_t)(m0 + m) * K + kb + k4 * 4];
            }
#pragma unroll
            for (int i = 0; i < 4; i++) {
                int f = tid + i * 256;
                int k = f >> 5, n4 = f & 31;
                rw[i] = *(const float4*)&W[(size_t)(kb + k) * NW + n0 + n4 * 4];
            }
        }

#pragma unroll
        for (int kk = 0; kk < 32; kk += 8) {
            wmma::fragment<wmma::matrix_a, 16, 16, 8, wmma::precision::tf32, wmma::row_major> a[2];
            wmma::fragment<wmma::matrix_b, 16, 16, 8, wmma::precision::tf32, wmma::row_major> b[4];
#pragma unroll
            for (int i = 0; i < 2; i++)
                wmma::load_matrix_sync(a[i], &As[(wm + i * 16) * LDA + kk], LDA);
#pragma unroll
            for (int j = 0; j < 4; j++)
                wmma::load_matrix_sync(b[j], &Ws[kk * LDW + wn + j * 16], LDW);
#pragma unroll
            for (int i = 0; i < 2; i++)
#pragma unroll
                for (int j = 0; j < 4; j++)
                    wmma::mma_sync(acc[i][j], a[i], b[j], acc[i][j]);
        }
        __syncthreads();
    }
}

// stage one 64-row wave (wave 0: block rows 0..63, wave 1: 64..127)
__device__ __forceinline__ void stage_wave(
    char* sh, wmma::fragment<wmma::accumulator, 16, 16, 8, float> acc[2][4], int wave)
{
    float* stage = (float*)sh;
    const int wid = threadIdx.x >> 5;
    const int wn  = (wid >> 2) * 64;
    if (((wid & 3) >> 1) == wave) {
        int wm = ((wid & 3) & 1) * 32;          // row offset within the wave
#pragma unroll
        for (int i = 0; i < 2; i++)
#pragma unroll
            for (int j = 0; j < 4; j++)
                wmma::store_matrix_sync(&stage[(wm + i * 16) * 128 + wn + j * 16],
                                        acc[i][j], 128, wmma::mem_row_major);
    }
    __syncthreads();
}

// GEMM 0: g_xn = rsqrt(deg+1)[row] * (state @ W_gcn)
__global__ void __launch_bounds__(256)
mma0_kernel(const float* __restrict__ state, const float* __restrict__ W_gcn, int M)
{
    __shared__ __align__(16) char sh[SMEM_GEMM];
    wmma::fragment<wmma::accumulator, 16, 16, 8, float> acc[2][4];
    const int m0 = blockIdx.x * 128;
    wmma_core<CDIM, CDIM>(state, W_gcn, sh, m0, 0, M, acc);
    float* stage = (float*)sh;
    const int tid = threadIdx.x;
#pragma unroll
    for (int wave = 0; wave < 2; wave++) {
        stage_wave(sh, acc, wave);
#pragma unroll
        for (int i = 0; i < 8; i++) {
            int f = tid + i * 256;
            int rw = f >> 5, c4 = f & 31;
            int r = m0 + wave * 64 + rw;
            if (r < M) {
                float d = rsqrtf((float)(g_deg[r] + 1));
                float4 v = *(float4*)&stage[rw * 128 + c4 * 4];
                v.x *= d; v.y *= d; v.z *= d; v.w *= d;
                *(float4*)&g_xn[(size_t)r * CDIM + c4 * 4] = v;
            }
        }
        __syncthreads();
    }
}

// GEMM 1: g_h1 = relu(g_y @ W1 + b1)
__global__ void __launch_bounds__(256)
gemm1_kernel(const float* __restrict__ W1, const float* __restrict__ b1, int M)
{
    __shared__ __align__(16) char sh[SMEM_GEMM];
    wmma::fragment<wmma::accumulator, 16, 16, 8, float> acc[2][4];
    const int m0 = blockIdx.x * 128, n0 = blockIdx.y * 128;
    wmma_core<CDIM, HDIM>(g_y, W1, sh, m0, n0, M, acc);
    float* stage = (float*)sh;
    const int tid = threadIdx.x;
#pragma unroll
    for (int wave = 0; wave < 2; wave++) {
        stage_wave(sh, acc, wave);
#pragma unroll
        for (int i = 0; i < 8; i++) {
            int f = tid + i * 256;
            int rw = f >> 5, c4 = f & 31;
            int r = m0 + wave * 64 + rw;
            if (r < M) {
                float4 b = *(const float4*)&b1[n0 + c4 * 4];
                float4 v = *(float4*)&stage[rw * 128 + c4 * 4];
                v.x = fmaxf(v.x + b.x, 0.f); v.y = fmaxf(v.y + b.y, 0.f);
                v.z = fmaxf(v.z + b.z, 0.f); v.w = fmaxf(v.w + b.w, 0.f);
                *(float4*)&g_h1[(size_t)r * HDIM + n0 + c4 * 4] = v;
            }
        }
        __syncthreads();
    }
}

// GEMM 2: out[r] += sum_j relu((g_h1 @ W2 + b2))[r][j] * W3[j]
__global__ void __launch_bounds__(256)
gemm2_kernel(const float* __restrict__ W2, const float* __restrict__ b2,
             const float* __restrict__ W3, float* __restrict__ out, int M)
{
    __shared__ __align__(16) char sh[SMEM_GEMM];
    wmma::fragment<wmma::accumulator, 16, 16, 8, float> acc[2][4];
    const int m0 = blockIdx.x * 128, n0 = blockIdx.y * 128;
    wmma_core<HDIM, HDIM>(g_h1, W2, sh, m0, n0, M, acc);
    float* stage = (float*)sh;
    const int wid = threadIdx.x >> 5, lane = threadIdx.x & 31;
    const int c0 = n0 + lane * 4;
    float4 b  = *(const float4*)&b2[c0];
    float4 w3 = *(const float4*)&W3[c0];
#pragma unroll
    for (int wave = 0; wave < 2; wave++) {
        stage_wave(sh, acc, wave);
#pragma unroll
        for (int i = 0; i < 8; i++) {
            int rw = wid * 8 + i;
            float4 v = *(float4*)&stage[rw * 128 + lane * 4];
            float p = fmaxf(v.x + b.x, 0.f) * w3.x
                    + fmaxf(v.y + b.y, 0.f) * w3.y
                    + fmaxf(v.z + b.z, 0.f) * w3.z
                    + fmaxf(v.w + b.w, 0.f) * w3.w;
#pragma unroll
            for (int s = 16; s > 0; s >>= 1) p += __shfl_xor_sync(~0u, p, s);
            int r = m0 + wave * 64 + rw;
            if (lane == 0 && r < M) atomicAdd(&out[r], p);
        }
        __syncthreads();
    }
}

// ---------------- fused CSR aggregate + readout -------------------------------
__global__ void readout_kernel(const float* __restrict__ state,
                               const float* __restrict__ action,
                               const float* __restrict__ b_gcn, int B)
{
    int idx = blockIdx.x * blockDim.x + threadIdx.x;
    int b = idx >> 5, lane = idx & 31;
    if (b >= B) return;
    int c0 = lane * 4;
    float4 bg = *(const float4*)&b_gcn[c0];
    float4 y = make_float4(0.f, 0.f, 0.f, 0.f);
#pragma unroll
    for (int a = 0; a < ADIM; a++) {
        int n = b * ADIM + a;
        float w  = action[b * ADIM + a] * 10.0f;
        int cnt = g_deg[n];
        float dn = rsqrtf((float)(cnt + 1));
        float4 agg = *(const float4*)&g_xn[(size_t)n * CDIM + c0];
        int st = g_rowptr[n];
        for (int k = 0; k < cnt; k++) {
            int s = g_col[st + k];
            float4 v = *(const float4*)&g_xn[(size_t)s * CDIM + c0];
            agg.x += v.x; agg.y += v.y; agg.z += v.z; agg.w += v.w;
        }
        float4 stt = *(const float4*)&state[(size_t)n * CDIM + c0];
        y.x += w * (fmaxf(dn * agg.x + bg.x, 0.f) + stt.x);
        y.y += w * (fmaxf(dn * agg.y + bg.y, 0.f) + stt.y);
        y.z += w * (fmaxf(dn * agg.z + bg.z, 0.f) + stt.z);
        y.w += w * (fmaxf(dn * agg.w + bg.w, 0.f) + stt.w);
    }
    *(float4*)&g_y[(size_t)b * CDIM + c0] = y;
}

// ---------------- launch ------------------------------------------------------
extern "C" void kernel_launch(void* const* d_in, const int* in_sizes, int n_in,
                              void* d_out, int out_size)
{
    const float* state  = (const float*)d_in[0];
    const int*   ei     = (const int*)d_in[1];   // int32 (JAX x64 disabled)
    const float* action = (const float*)d_in[2];
    const float* W_gcn  = (const float*)d_in[3];
    const float* b_gcn  = (const float*)d_in[4];
    const float* W1     = (const float*)d_in[5];
    const float* b1     = (const float*)d_in[6];
    const float* W2     = (const float*)d_in[7];
    const float* b2     = (const float*)d_in[8];
    const float* W3     = (const float*)d_in[9];
    const float* b3     = (const float*)d_in[10];
    float* out = (float*)d_out;

    const int N = in_sizes[0] / CDIM;
    const int E = in_sizes[1] / 2;
    const int B = N / ADIM;

    const int* esrc = ei;
    const int* edst = ei + E;
    const int NB = (N + 1023) / 1024;

    // ncu empirically captures launch #4 -> place mma0 there
    zero_deg_kernel <<<(N + 255) / 256, 256>>>(N);                 // 1
    count_deg_kernel<<<(E + 255) / 256, 256>>>(edst, E, N);        // 2
    scan1_kernel<<<NB, 256>>>(N);                                  // 3
    mma0_kernel<<<(N + 127) / 128, 256>>>(state, W_gcn, N);        // 4 <- profiled
    scan2_kernel<<<1, 512>>>(NB);                                  // 5
    scan3_kernel<<<NB, 256>>>(N);                                  // 6
    fill_kernel <<<(E + 255) / 256, 256>>>(esrc, edst, E, N);      // 7
    {
        long long threads = (long long)B * 32;
        readout_kernel<<<(int)((threads + 255) / 256), 256>>>(state, action, b_gcn, B);
    }
    {
        dim3 grid((B + 127) / 128, HDIM / 128);
        gemm1_kernel<<<grid, 256>>>(W1, b1, B);
    }
    init_out_kernel<<<(B + 255) / 256, 256>>>(out, b3, B);
    {
        dim3 grid((B + 127) / 128, HDIM / 128);
        gemm2_kernel<<<grid, 256>>>(W2, b2, W3, out, B);
    }
}

// round 10
// speedup vs baseline: 1.2097x; 1.2097x over previous
#include <cuda_runtime.h>
#include <mma.h>
#include <cstdint>

using namespace nvcuda;

#define NNODES 500000
#define CDIM   128
#define HDIM   256
#define ADIM   10
#define BROWS  (NNODES / ADIM)
#define EMAX   600000

// ---------------- scratch (device globals) -----------------------------------
__device__ __align__(16) float g_xn [(size_t)NNODES * CDIM];
__device__ __align__(16) float g_y  [(size_t)BROWS * CDIM];
__device__ __align__(16) float g_h1 [(size_t)BROWS * HDIM];
__device__ int   g_deg[NNODES];
__device__ int   g_rowptr[NNODES];
__device__ int   g_cursor[NNODES];
__device__ int   g_col[EMAX];
__device__ int   g_bsum[1024];

// ---------------- small kernels ----------------------------------------------
__global__ void zero_deg_kernel(int n) {
    int i = blockIdx.x * blockDim.x + threadIdx.x;
    if (i < n) g_deg[i] = 0;
}
__global__ void count_deg_kernel(const int* __restrict__ dst, int E, int N) {
    int e = blockIdx.x * blockDim.x + threadIdx.x;
    if (e < E) {
        int d = dst[e];
        if (d >= 0 && d < N) atomicAdd(&g_deg[d], 1);
    }
}
__global__ void init_out_kernel(float* __restrict__ out, const float* __restrict__ b3, int B) {
    int i = blockIdx.x * blockDim.x + threadIdx.x;
    if (i < B) out[i] = b3[0];
}

// ---------------- prefix scan (3 kernels) -------------------------------------
__global__ void __launch_bounds__(256) scan1_kernel(int n) {
    __shared__ int warp_sums[8];
    const int tid = threadIdx.x, lane = tid & 31, wid = tid >> 5;
    const int gbase = blockIdx.x * 1024 + tid * 4;
    int v[4]; int t = 0;
#pragma unroll
    for (int j = 0; j < 4; j++) { v[j] = (gbase + j < n) ? g_deg[gbase + j] : 0; t += v[j]; }
    int inc = t;
#pragma unroll
    for (int o = 1; o < 32; o <<= 1) { int x = __shfl_up_sync(~0u, inc, o); if (lane >= o) inc += x; }
    if (lane == 31) warp_sums[wid] = inc;
    __syncthreads();
    if (wid == 0) {
        int ws = (lane < 8) ? warp_sums[lane] : 0;
#pragma unroll
        for (int o = 1; o < 8; o <<= 1) { int x = __shfl_up_sync(~0u, ws, o); if (lane >= o) ws += x; }
        if (lane < 8) warp_sums[lane] = ws;
    }
    __syncthreads();
    int block_excl = (wid > 0) ? warp_sums[wid - 1] : 0;
    int run = block_excl + inc - t;
#pragma unroll
    for (int j = 0; j < 4; j++) { if (gbase + j < n) g_rowptr[gbase + j] = run; run += v[j]; }
    if (tid == 0) g_bsum[blockIdx.x] = warp_sums[7];
}
__global__ void __launch_bounds__(512) scan2_kernel(int nb) {
    __shared__ int sh[512];
    const int tid = threadIdx.x;
    int v = (tid < nb) ? g_bsum[tid] : 0;
    sh[tid] = v;
    __syncthreads();
    for (int o = 1; o < 512; o <<= 1) {
        int x = (tid >= o) ? sh[tid - o] : 0;
        __syncthreads();
        sh[tid] += x;
        __syncthreads();
    }
    if (tid < nb) g_bsum[tid] = sh[tid] - v;
}
__global__ void __launch_bounds__(256) scan3_kernel(int n) {
    const int gbase = blockIdx.x * 1024 + threadIdx.x * 4;
    const int off = g_bsum[blockIdx.x];
#pragma unroll
    for (int j = 0; j < 4; j++) {
        int i = gbase + j;
        if (i < n) { int r = g_rowptr[i] + off; g_rowptr[i] = r; g_cursor[i] = r; }
    }
}
__global__ void fill_kernel(const int* __restrict__ src, const int* __restrict__ dst,
                            int E, int N) {
    int e = blockIdx.x * blockDim.x + threadIdx.x;
    if (e >= E) return;
    int d = dst[e], s = src[e];
    if (d < 0 || d >= N || s < 0 || s >= N) return;
    int pos = atomicAdd(&g_cursor[d], 1);
    if (pos >= 0 && pos < EMAX) g_col[pos] = s;
}

// ---------------- wmma tf32 GEMM core v4 ---------------------------------------
// Block 256 thr (8 warps, 2M x 4N). Tile 64x128, warp tile 32x32, K-chunks 32.
// v4: double-buffered DYNAMIC smem -> ONE __syncthreads per chunk.
//     tf32 cvt at SMEM store; register prefetch overlaps LDG with MMA stage.
//     __launch_bounds__(256,2) caps regs at 128 -> 2 blocks/SM (occ 25%).
#define LDA 36
#define LDW 132
#define OFF_WS (64 * LDA * 4)                 // 9216 B
#define BUFSZ  ((OFF_WS + 32 * LDW * 4 + 511) & ~511)   // 26624 B
#define SMEM_DB (2 * BUFSZ)                   // 53248 B (dynamic)

template <int K, int NW>
__device__ __forceinline__ void wmma_core(
    const float* __restrict__ A, const float* __restrict__ W,
    char* sh, int m0, int n0, int M,
    wmma::fragment<wmma::accumulator, 16, 16, 8, float> acc[2][2])
{
    const int tid = threadIdx.x;
    const int wid = tid >> 5;
    const int wm  = (wid & 1) * 32;
    const int wn  = (wid >> 1) * 32;

#pragma unroll
    for (int i = 0; i < 2; i++)
#pragma unroll
        for (int j = 0; j < 2; j++) wmma::fill_fragment(acc[i][j], 0.0f);

    float4 ra[2], rw[4];

    // chunk 0 -> regs -> buf0
#pragma unroll
    for (int i = 0; i < 2; i++) {
        int f = tid * 2 + i;
        int m = f >> 3, k4 = f & 7;
        ra[i] = make_float4(0.f, 0.f, 0.f, 0.f);
        if (m0 + m < M)
            ra[i] = *(const float4*)&A[(size_t)(m0 + m) * K + k4 * 4];
    }
#pragma unroll
    for (int i = 0; i < 4; i++) {
        int f = tid + i * 256;
        int k = f >> 5, n4 = f & 31;
        rw[i] = *(const float4*)&W[(size_t)k * NW + n0 + n4 * 4];
    }
    {
        float* As0 = (float*)sh;
        float* Ws0 = (float*)(sh + OFF_WS);
#pragma unroll
        for (int i = 0; i < 2; i++) {
            int f = tid * 2 + i;
            int m = f >> 3, k4 = f & 7;
            float4 v = ra[i];
            v.x = wmma::__float_to_tf32(v.x); v.y = wmma::__float_to_tf32(v.y);
            v.z = wmma::__float_to_tf32(v.z); v.w = wmma::__float_to_tf32(v.w);
            *(float4*)&As0[m * LDA + k4 * 4] = v;
        }
#pragma unroll
        for (int i = 0; i < 4; i++) {
            int f = tid + i * 256;
            int k = f >> 5, n4 = f & 31;
            float4 v = rw[i];
            v.x = wmma::__float_to_tf32(v.x); v.y = wmma::__float_to_tf32(v.y);
            v.z = wmma::__float_to_tf32(v.z); v.w = wmma::__float_to_tf32(v.w);
            *(float4*)&Ws0[k * LDW + n4 * 4] = v;
        }
    }
    __syncthreads();

    const int nchunks = K / 32;
    for (int c = 0; c < nchunks; c++) {
        char* cur = sh + (c & 1) * BUFSZ;
        char* nxt = sh + ((c + 1) & 1) * BUFSZ;
        float* As = (float*)cur;
        float* Ws = (float*)(cur + OFF_WS);

        // prefetch next chunk (LDGs overlap the MMA stage below)
        if (c + 1 < nchunks) {
            int kb = (c + 1) * 32;
#pragma unroll
            for (int i = 0; i < 2; i++) {
                int f = tid * 2 + i;
                int m = f >> 3, k4 = f & 7;
                ra[i] = make_float4(0.f, 0.f, 0.f, 0.f);
                if (m0 + m < M)
                    ra[i] = *(const float4*)&A[(size_t)(m0 + m) * K + kb + k4 * 4];
            }
#pragma unroll
            for (int i = 0; i < 4; i++) {
                int f = tid + i * 256;
                int k = f >> 5, n4 = f & 31;
                rw[i] = *(const float4*)&W[(size_t)(kb + k) * NW + n0 + n4 * 4];
            }
        }

        // MMA stage on current buffer
#pragma unroll
        for (int kk = 0; kk < 32; kk += 8) {
            wmma::fragment<wmma::matrix_a, 16, 16, 8, wmma::precision::tf32, wmma::row_major> a[2];
            wmma::fragment<wmma::matrix_b, 16, 16, 8, wmma::precision::tf32, wmma::row_major> b[2];
#pragma unroll
            for (int i = 0; i < 2; i++)
                wmma::load_matrix_sync(a[i], &As[(wm + i * 16) * LDA + kk], LDA);
#pragma unroll
            for (int j = 0; j < 2; j++)
                wmma::load_matrix_sync(b[j], &Ws[kk * LDW + wn + j * 16], LDW);
#pragma unroll
            for (int i = 0; i < 2; i++)
#pragma unroll
                for (int j = 0; j < 2; j++)
                    wmma::mma_sync(acc[i][j], a[i], b[j], acc[i][j]);
        }

        // store next chunk into the other buffer (cvt once per element)
        if (c + 1 < nchunks) {
            float* Asn = (float*)nxt;
            float* Wsn = (float*)(nxt + OFF_WS);
#pragma unroll
            for (int i = 0; i < 2; i++) {
                int f = tid * 2 + i;
                int m = f >> 3, k4 = f & 7;
                float4 v = ra[i];
                v.x = wmma::__float_to_tf32(v.x); v.y = wmma::__float_to_tf32(v.y);
                v.z = wmma::__float_to_tf32(v.z); v.w = wmma::__float_to_tf32(v.w);
                *(float4*)&Asn[m * LDA + k4 * 4] = v;
            }
#pragma unroll
            for (int i = 0; i < 4; i++) {
                int f = tid + i * 256;
                int k = f >> 5, n4 = f & 31;
                float4 v = rw[i];
                v.x = wmma::__float_to_tf32(v.x); v.y = wmma::__float_to_tf32(v.y);
                v.z = wmma::__float_to_tf32(v.z); v.w = wmma::__float_to_tf32(v.w);
                *(float4*)&Wsn[k * LDW + n4 * 4] = v;
            }
        }
        __syncthreads();   // single sync per chunk
    }
}

__device__ __forceinline__ void stage_acc(
    char* sh, wmma::fragment<wmma::accumulator, 16, 16, 8, float> acc[2][2])
{
    float* stage = (float*)sh;
    const int wid = threadIdx.x >> 5;
    const int wm  = (wid & 1) * 32;
    const int wn  = (wid >> 1) * 32;
#pragma unroll
    for (int i = 0; i < 2; i++)
#pragma unroll
        for (int j = 0; j < 2; j++)
            wmma::store_matrix_sync(&stage[(wm + i * 16) * 128 + wn + j * 16],
                                    acc[i][j], 128, wmma::mem_row_major);
    __syncthreads();
}

// GEMM 0: g_xn = rsqrt(deg+1)[row] * (state @ W_gcn)
__global__ void __launch_bounds__(256, 2)
mma0_kernel(const float* __restrict__ state, const float* __restrict__ W_gcn, int M)
{
    extern __shared__ __align__(16) char dsh[];
    wmma::fragment<wmma::accumulator, 16, 16, 8, float> acc[2][2];
    const int m0 = blockIdx.x * 64;
    wmma_core<CDIM, CDIM>(state, W_gcn, dsh, m0, 0, M, acc);
    stage_acc(dsh, acc);
    float* stage = (float*)dsh;
    const int tid = threadIdx.x;
#pragma unroll
    for (int i = 0; i < 8; i++) {
        int f = tid + i * 256;
        int rw = f >> 5, c4 = f & 31;
        int r = m0 + rw;
        if (r < M) {
            float d = rsqrtf((float)(g_deg[r] + 1));
            float4 v = *(float4*)&stage[rw * 128 + c4 * 4];
            v.x *= d; v.y *= d; v.z *= d; v.w *= d;
            *(float4*)&g_xn[(size_t)r * CDIM + c4 * 4] = v;
        }
    }
}

// GEMM 1: g_h1 = relu(g_y @ W1 + b1)
__global__ void __launch_bounds__(256, 2)
gemm1_kernel(const float* __restrict__ W1, const float* __restrict__ b1, int M)
{
    extern __shared__ __align__(16) char dsh[];
    wmma::fragment<wmma::accumulator, 16, 16, 8, float> acc[2][2];
    const int m0 = blockIdx.x * 64, n0 = blockIdx.y * 128;
    wmma_core<CDIM, HDIM>(g_y, W1, dsh, m0, n0, M, acc);
    stage_acc(dsh, acc);
    float* stage = (float*)dsh;
    const int tid = threadIdx.x;
#pragma unroll
    for (int i = 0; i < 8; i++) {
        int f = tid + i * 256;
        int rw = f >> 5, c4 = f & 31;
        int r = m0 + rw;
        if (r < M) {
            float4 b = *(const float4*)&b1[n0 + c4 * 4];
            float4 v = *(float4*)&stage[rw * 128 + c4 * 4];
            v.x = fmaxf(v.x + b.x, 0.f); v.y = fmaxf(v.y + b.y, 0.f);
            v.z = fmaxf(v.z + b.z, 0.f); v.w = fmaxf(v.w + b.w, 0.f);
            *(float4*)&g_h1[(size_t)r * HDIM + n0 + c4 * 4] = v;
        }
    }
}

// GEMM 2: out[r] += sum_j relu((g_h1 @ W2 + b2))[r][j] * W3[j]
__global__ void __launch_bounds__(256, 2)
gemm2_kernel(const float* __restrict__ W2, const float* __restrict__ b2,
             const float* __restrict__ W3, float* __restrict__ out, int M)
{
    extern __shared__ __align__(16) char dsh[];
    wmma::fragment<wmma::accumulator, 16, 16, 8, float> acc[2][2];
    const int m0 = blockIdx.x * 64, n0 = blockIdx.y * 128;
    wmma_core<HDIM, HDIM>(g_h1, W2, dsh, m0, n0, M, acc);
    stage_acc(dsh, acc);
    float* stage = (float*)dsh;
    const int wid = threadIdx.x >> 5, lane = threadIdx.x & 31;
    const int c0 = n0 + lane * 4;
    float4 b  = *(const float4*)&b2[c0];
    float4 w3 = *(const float4*)&W3[c0];
#pragma unroll
    for (int i = 0; i < 8; i++) {
        int rw = wid * 8 + i;
        float4 v = *(float4*)&stage[rw * 128 + lane * 4];
        float p = fmaxf(v.x + b.x, 0.f) * w3.x
                + fmaxf(v.y + b.y, 0.f) * w3.y
                + fmaxf(v.z + b.z, 0.f) * w3.z
                + fmaxf(v.w + b.w, 0.f) * w3.w;
#pragma unroll
        for (int s = 16; s > 0; s >>= 1) p += __shfl_xor_sync(~0u, p, s);
        int r = m0 + rw;
        if (lane == 0 && r < M) atomicAdd(&out[r], p);
    }
}

// ---------------- fused CSR aggregate + readout -------------------------------
__global__ void readout_kernel(const float* __restrict__ state,
                               const float* __restrict__ action,
                               const float* __restrict__ b_gcn, int B)
{
    int idx = blockIdx.x * blockDim.x + threadIdx.x;
    int b = idx >> 5, lane = idx & 31;
    if (b >= B) return;
    int c0 = lane * 4;
    float4 bg = *(const float4*)&b_gcn[c0];
    float4 y = make_float4(0.f, 0.f, 0.f, 0.f);
#pragma unroll
    for (int a = 0; a < ADIM; a++) {
        int n = b * ADIM + a;
        float w  = action[b * ADIM + a] * 10.0f;
        int cnt = g_deg[n];
        float dn = rsqrtf((float)(cnt + 1));
        float4 agg = *(const float4*)&g_xn[(size_t)n * CDIM + c0];
        int st = g_rowptr[n];
        for (int k = 0; k < cnt; k++) {
            int s = g_col[st + k];
            float4 v = *(const float4*)&g_xn[(size_t)s * CDIM + c0];
            agg.x += v.x; agg.y += v.y; agg.z += v.z; agg.w += v.w;
        }
        float4 stt = *(const float4*)&state[(size_t)n * CDIM + c0];
        y.x += w * (fmaxf(dn * agg.x + bg.x, 0.f) + stt.x);
        y.y += w * (fmaxf(dn * agg.y + bg.y, 0.f) + stt.y);
        y.z += w * (fmaxf(dn * agg.z + bg.z, 0.f) + stt.z);
        y.w += w * (fmaxf(dn * agg.w + bg.w, 0.f) + stt.w);
    }
    *(float4*)&g_y[(size_t)b * CDIM + c0] = y;
}

// ---------------- launch ------------------------------------------------------
extern "C" void kernel_launch(void* const* d_in, const int* in_sizes, int n_in,
                              void* d_out, int out_size)
{
    const float* state  = (const float*)d_in[0];
    const int*   ei     = (const int*)d_in[1];   // int32 (JAX x64 disabled)
    const float* action = (const float*)d_in[2];
    const float* W_gcn  = (const float*)d_in[3];
    const float* b_gcn  = (const float*)d_in[4];
    const float* W1     = (const float*)d_in[5];
    const float* b1     = (const float*)d_in[6];
    const float* W2     = (const float*)d_in[7];
    const float* b2     = (const float*)d_in[8];
    const float* W3     = (const float*)d_in[9];
    const float* b3     = (const float*)d_in[10];
    float* out = (float*)d_out;

    const int N = in_sizes[0] / CDIM;
    const int E = in_sizes[1] / 2;
    const int B = N / ADIM;

    const int* esrc = ei;
    const int* edst = ei + E;
    const int NB = (N + 1023) / 1024;

    static int attr_done = 0;
    if (!attr_done) {
        cudaFuncSetAttribute(mma0_kernel,  cudaFuncAttributeMaxDynamicSharedMemorySize, SMEM_DB);
        cudaFuncSetAttribute(gemm1_kernel, cudaFuncAttributeMaxDynamicSharedMemorySize, SMEM_DB);
        cudaFuncSetAttribute(gemm2_kernel, cudaFuncAttributeMaxDynamicSharedMemorySize, SMEM_DB);
        attr_done = 1;
    }

    // ncu captures launch #4 -> mma0 there
    zero_deg_kernel <<<(N + 255) / 256, 256>>>(N);                    // 1
    count_deg_kernel<<<(E + 255) / 256, 256>>>(edst, E, N);           // 2
    scan1_kernel<<<NB, 256>>>(N);                                     // 3
    mma0_kernel<<<(N + 63) / 64, 256, SMEM_DB>>>(state, W_gcn, N);    // 4 <- profiled
    scan2_kernel<<<1, 512>>>(NB);                                     // 5
    scan3_kernel<<<NB, 256>>>(N);                                     // 6
    fill_kernel <<<(E + 255) / 256, 256>>>(esrc, edst, E, N);         // 7
    {
        long long threads = (long long)B * 32;
        readout_kernel<<<(int)((threads + 255) / 256), 256>>>(state, action, b_gcn, B);
    }
    {
        dim3 grid((B + 63) / 64, HDIM / 128);
        gemm1_kernel<<<grid, 256, SMEM_DB>>>(W1, b1, B);
    }
    init_out_kernel<<<(B + 255) / 256, 256>>>(out, b3, B);
    {
        dim3 grid((B + 63) / 64, HDIM / 128);
        gemm2_kernel<<<grid, 256, SMEM_DB>>>(W2, b2, W3, out, B);
    }
}